// round 6
// baseline (speedup 1.0000x reference)
#include <cuda_runtime.h>

// Correlation (FlowNet), max_displacement=40:
//   out[b, dy*81+dx, h, w] = (1/sqrt(128)) * sum_c x1[b,c,h,w] * x2pad[b,c,h+dy,w+dx]
// x1,x2 = (2,128,64,96) f32; out = (2,6561,64,96) f32.
//
// R4: 4dx x 8w register tiles (16B-grain window offsets -> all 8 smem bank
// groups, ~conflict-free), dg-major lane map, 504 threads (2-way C split),
// FFMA2 via fma.rn.f32x2.

#define MD    40
#define KD    81          // 2*MD+1
#define C     128
#define H     64
#define W     96
#define WPS   192         // padded smem row stride for x2 window
#define NDG   21          // dx groups of 4 (dg=20 -> only dx=80 valid)
#define NWG   12          // w groups of 8
#define NTILE (NDG*NWG)   // 252
#define NT    (NTILE*2)   // 504 threads: 2 c-chunks of 64
#define SMEM_BYTES ((C*W + C*WPS) * 4)   // 147456 B

typedef unsigned long long u64;

__device__ __forceinline__ u64 pack2(float lo, float hi) {
    u64 r; asm("mov.b64 %0, {%1, %2};" : "=l"(r) : "f"(lo), "f"(hi)); return r;
}
__device__ __forceinline__ void fma2(u64& d, u64 a, u64 b) {
    asm("fma.rn.f32x2 %0, %1, %2, %0;" : "+l"(d) : "l"(a), "l"(b));
}
__device__ __forceinline__ float2 unpack2(u64 v) {
    float2 r; asm("mov.b64 {%0, %1}, %2;" : "=f"(r.x), "=f"(r.y) : "l"(v)); return r;
}

__global__ __launch_bounds__(NT, 1)
void corr_kernel(const float* __restrict__ x1,
                 const float* __restrict__ x2,
                 float* __restrict__ out)
{
    extern __shared__ float sm[];
    float* s1 = sm;                 // [C][W]   x1 row at (b, h)
    float* s2 = sm + C * W;         // [C][WPS] zero-padded x2 row at (b, h+dy-MD)

    const int dy  = blockIdx.x;     // 0..80
    const int h   = blockIdx.y;     // 0..63
    const int b   = blockIdx.z;     // 0..1
    const int tid = threadIdx.x;

    const int h2 = h + dy - MD;

    if (h2 < 0 || h2 >= H) {
        // Entire (b, h, dy, *) slab is zero: 81 dx rows of 96 floats.
        const size_t base = (((size_t)b * (KD * KD) + (size_t)dy * KD) * H + h) * W;
        const float4 z = make_float4(0.f, 0.f, 0.f, 0.f);
        for (int i = tid; i < KD * (W / 4); i += NT) {
            const int dx = i / (W / 4);
            const int w4 = i % (W / 4);
            *(float4*)(out + base + (size_t)dx * (H * W) + w4 * 4) = z;
        }
        return;
    }

    // ---- stage x1 row and padded x2 row into shared memory (float4) ----
    const float* x1b = x1 + ((size_t)b * C * H + h)  * W;
    const float* x2b = x2 + ((size_t)b * C * H + h2) * W;

    for (int i = tid; i < C * (W / 4); i += NT) {
        const int c = i / (W / 4), q = i % (W / 4);
        *(float4*)(s1 + c * W + q * 4) = *(const float4*)(x1b + (size_t)c * (H * W) + q * 4);
    }
    const float4 z4 = make_float4(0.f, 0.f, 0.f, 0.f);
    for (int i = tid; i < C * (WPS / 4); i += NT) {
        const int c = i / (WPS / 4), q = i % (WPS / 4);
        // valid scalar range wp in [MD, MD+W) = [40,136) -> float4 chunks 10..33
        float4 v = z4;
        if (q >= MD / 4 && q < (MD + W) / 4)
            v = *(const float4*)(x2b + (size_t)c * (H * W) + (q * 4 - MD));
        *(float4*)(s2 + c * WPS + q * 4) = v;
    }
    __syncthreads();

    // ---- tile / c-chunk mapping ----
    // tile = dg*12 + wgi: within a warp, wgi runs fastest -> a-loads are
    // consecutive/broadcast; b-window offsets 8*wgi+4*dg hit 16B-grain
    // sectors across all 8 bank groups -> minimal conflicts.
    const int cchunk = tid / NTILE;          // 0 or 1 (c in [cchunk*64, +64))
    const int tile   = tid - cchunk * NTILE; // 0..251
    const int dg     = tile / NWG;           // 0..20 -> dx0 = 4*dg
    const int wgi    = tile - dg * NWG;      // 0..11 -> w0  = 8*wgi
    const int w0     = wgi * 8;
    const int dx0    = dg * 4;

    u64 acc[4][4];                           // [d][w-pair]
#pragma unroll
    for (int d = 0; d < 4; ++d)
#pragma unroll
        for (int j = 0; j < 4; ++j) acc[d][j] = 0ull;

    const float* p1 = s1 + w0;               // 32B-aligned
    const float* p2 = s2 + w0 + dx0;         // 16B-aligned
    const int cb = cchunk * 64;

#pragma unroll 4
    for (int cc = 0; cc < 64; ++cc) {
        const float* r1 = p1 + (size_t)(cb + cc) * W;
        const float* r2 = p2 + (size_t)(cb + cc) * WPS;

        const float4 a0 = *(const float4*)(r1);
        const float4 a1 = *(const float4*)(r1 + 4);
        const float4 b0 = *(const float4*)(r2);       // floats 0..3
        const float4 b1 = *(const float4*)(r2 + 4);   // floats 4..7
        const float4 b2 = *(const float4*)(r2 + 8);   // floats 8..11

        u64 A[4];
        A[0] = pack2(a0.x, a0.y); A[1] = pack2(a0.z, a0.w);
        A[2] = pack2(a1.x, a1.y); A[3] = pack2(a1.z, a1.w);

        const float f0 = b0.x, f1 = b0.y, f2 = b0.z, f3 = b0.w;
        const float f4 = b1.x, f5 = b1.y, f6 = b1.z, f7 = b1.w;
        const float f8 = b2.x, f9 = b2.y, f10 = b2.z;

        u64 B[5], S[5];
        B[0] = pack2(f0, f1); B[1] = pack2(f2, f3); B[2] = pack2(f4, f5);
        B[3] = pack2(f6, f7); B[4] = pack2(f8, f9);
        S[0] = pack2(f1, f2); S[1] = pack2(f3, f4); S[2] = pack2(f5, f6);
        S[3] = pack2(f7, f8); S[4] = pack2(f9, f10);

        // acc[d][j] covers (dx=dx0+d, w = w0+2j, w0+2j+1):
        //   even d -> B[d/2 + j], odd d -> S[(d-1)/2 + j]
#pragma unroll
        for (int j = 0; j < 4; ++j) {
            fma2(acc[0][j], A[j], B[j]);
            fma2(acc[1][j], A[j], S[j]);
            fma2(acc[2][j], A[j], B[j + 1]);
            fma2(acc[3][j], A[j], S[j + 1]);
        }
    }

    // ---- 2-way c-chunk reduction via smem (reuse staging region) ----
    __syncthreads();
    float* red = sm;   // layout [32 values][NTILE] -> lanes consecutive, conflict-free

    if (cchunk == 1) {
#pragma unroll
        for (int d = 0; d < 4; ++d)
#pragma unroll
            for (int j = 0; j < 4; ++j) {
                const float2 f = unpack2(acc[d][j]);
                red[(d * 8 + 2 * j)     * NTILE + tile] = f.x;
                red[(d * 8 + 2 * j + 1) * NTILE + tile] = f.y;
            }
    }
    __syncthreads();

    if (cchunk == 0) {
        const float scale = 0.08838834764831843f;   // 1/sqrt(128)
#pragma unroll
        for (int d = 0; d < 4; ++d) {
            const int dx = dx0 + d;
            if (dx < KD) {
                float o[8];
#pragma unroll
                for (int j = 0; j < 4; ++j) {
                    const float2 f = unpack2(acc[d][j]);
                    o[2 * j]     = f.x;
                    o[2 * j + 1] = f.y;
                }
#pragma unroll
                for (int k = 0; k < 8; ++k)
                    o[k] = (o[k] + red[(d * 8 + k) * NTILE + tile]) * scale;

                const size_t off =
                    (((size_t)b * (KD * KD) + (size_t)(dy * KD + dx)) * H + h) * W + w0;
                float4 v0, v1;
                v0.x = o[0]; v0.y = o[1]; v0.z = o[2]; v0.w = o[3];
                v1.x = o[4]; v1.y = o[5]; v1.z = o[6]; v1.w = o[7];
                *(float4*)(out + off)     = v0;
                *(float4*)(out + off + 4) = v1;
            }
        }
    }
}

extern "C" void kernel_launch(void* const* d_in, const int* in_sizes, int n_in,
                              void* d_out, int out_size)
{
    const float* x1 = (const float*)d_in[0];
    const float* x2 = (const float*)d_in[1];
    float* out = (float*)d_out;

    cudaFuncSetAttribute(corr_kernel, cudaFuncAttributeMaxDynamicSharedMemorySize, SMEM_BYTES);

    dim3 grid(KD, H, 2);     // (dy, h, b)
    corr_kernel<<<grid, NT, SMEM_BYTES>>>(x1, x2, out);
}

// round 8
// speedup vs baseline: 4.4567x; 4.4567x over previous
#include <cuda_runtime.h>
#include <cuda_bf16.h>
#include <cstdint>

// Correlation (FlowNet) via per-(b,h) Gram GEMMs on mma.sync (HMMA bf16).
//   out[b, dy*81+dx, h, w] = (1/sqrt(128)) * sum_c x1[b,c,h,w]*x2pad[b,c,h+dy,w+dx]
// D[w][w2] = sum_c x1[.,h,w]*x2[.,h2,w2]  (M=96, N=96, K=128, split-bf16 x3)
// out[dy][dx][w] = D[w][w+dx-40], h2 = h+dy-40.

#define MD 40
#define KD 81
#define C  128
#define H  64
#define W  96

#define IMG_HALF  24576                 // 96 rows * 256 B (bf16 [w][c], swizzled)
#define IMG_BYTES 49152                 // hi image + lo image

__device__ __align__(1024) unsigned char gA[(size_t)2 * H * IMG_BYTES];  // 6.3 MB
__device__ __align__(1024) unsigned char gB[(size_t)2 * H * IMG_BYTES];  // 6.3 MB

__device__ __forceinline__ uint32_t smem_u32(const void* p) {
    uint32_t a;
    asm("{ .reg .u64 t; cvta.to.shared.u64 t, %1; cvt.u32.u64 %0, t; }" : "=r"(a) : "l"(p));
    return a;
}
// swizzled byte offset of element (row=w, col=c) in a [96][128] bf16 image
__device__ __forceinline__ uint32_t swz(int row, int kbyte) {
    uint32_t off = row * 256 + kbyte;
    return off ^ ((row & 7) << 4);
}

#define CP16(sdst, gsrc) \
    asm volatile("cp.async.cg.shared.global [%0], [%1], 16;" \
        :: "r"(sdst), "l"(gsrc) : "memory")
#define CP_COMMIT() asm volatile("cp.async.commit_group;" ::: "memory")

#define LDMX4(r0,r1,r2,r3,a) \
    asm volatile("ldmatrix.sync.aligned.m8n8.x4.shared.b16 {%0,%1,%2,%3}, [%4];" \
        : "=r"(r0),"=r"(r1),"=r"(r2),"=r"(r3) : "r"(a))
#define LDMX2(r0,r1,a) \
    asm volatile("ldmatrix.sync.aligned.m8n8.x2.shared.b16 {%0,%1}, [%2];" \
        : "=r"(r0),"=r"(r1) : "r"(a))
#define MMA(d,a,b) \
    asm volatile("mma.sync.aligned.m16n8k16.row.col.f32.bf16.bf16.f32 " \
        "{%0,%1,%2,%3}, {%4,%5,%6,%7}, {%8,%9}, {%0,%1,%2,%3};" \
        : "+f"((d)[0]),"+f"((d)[1]),"+f"((d)[2]),"+f"((d)[3]) \
        : "r"((a)[0]),"r"((a)[1]),"r"((a)[2]),"r"((a)[3]), "r"((b)[0]),"r"((b)[1]))

// ---------------- kernel 1: build swizzled bf16 hi/lo images ----------------
#define STG_STRIDE 129
#define PREP_SMEM (96 * STG_STRIDE * 4 + IMG_BYTES)   // 49536 + 49152 = 98688

__global__ __launch_bounds__(256, 1)
void prep_kernel(const float* __restrict__ x1, const float* __restrict__ x2)
{
    extern __shared__ float ps[];                       // stage [w][STG_STRIDE] f32
    uint32_t* img = (uint32_t*)((unsigned char*)ps + 96 * STG_STRIDE * 4);

    const int h = blockIdx.x, b = blockIdx.y, tid = threadIdx.x;

    for (int t = 0; t < 2; t++) {
        const float* src = (t ? x2 : x1);
        // load row (b,:,h,:) -> stage[w][c]
        for (int i = tid; i < C * (W / 4); i += 256) {
            const int c = i / 24, q = i % 24;
            const float4 v = *(const float4*)(src + (((size_t)b * C + c) * H + h) * W + q * 4);
            ps[(q * 4 + 0) * STG_STRIDE + c] = v.x;
            ps[(q * 4 + 1) * STG_STRIDE + c] = v.y;
            ps[(q * 4 + 2) * STG_STRIDE + c] = v.z;
            ps[(q * 4 + 3) * STG_STRIDE + c] = v.w;
        }
        __syncthreads();
        // build hi/lo bf16 image, two c per thread (one 4B word)
        for (int i = tid; i < W * (C / 2); i += 256) {
            const int w = i >> 6, c2 = i & 63;
            const float f0 = ps[w * STG_STRIDE + 2 * c2];
            const float f1 = ps[w * STG_STRIDE + 2 * c2 + 1];
            const __nv_bfloat16 h0 = __float2bfloat16(f0);
            const __nv_bfloat16 h1 = __float2bfloat16(f1);
            const __nv_bfloat16 l0 = __float2bfloat16(f0 - __bfloat162float(h0));
            const __nv_bfloat16 l1 = __float2bfloat16(f1 - __bfloat162float(h1));
            const uint32_t hw = ((uint32_t)__bfloat16_as_ushort(h1) << 16) | __bfloat16_as_ushort(h0);
            const uint32_t lw = ((uint32_t)__bfloat16_as_ushort(l1) << 16) | __bfloat16_as_ushort(l0);
            const uint32_t sw = swz(w, c2 * 4);
            img[sw >> 2]                    = hw;
            img[(IMG_HALF + sw) >> 2]       = lw;
        }
        __syncthreads();
        // linear copy image -> gmem
        {
            unsigned char* gdst = (t ? gB : gA) + ((size_t)b * H + h) * IMG_BYTES;
            uint4* d4 = (uint4*)gdst;
            const uint4* s4 = (const uint4*)img;
            for (int i = tid; i < IMG_BYTES / 16; i += 256) d4[i] = s4[i];
        }
        __syncthreads();
    }
}

// ---------------- kernel 2: HMMA GEMM + epilogue ----------------
// smem: A img [0,49152) ; B slots [49152,147456) ; Dstage [147456, +39936)
#define SB_OFF   IMG_BYTES
#define SD_OFF   (3 * IMG_BYTES)                 // 147456
#define DSTRIDE  104
#define MAIN_SMEM (SD_OFF + 96 * DSTRIDE * 4)    // 187392

__global__ __launch_bounds__(256, 1)
void corr_main(float* __restrict__ out)
{
    extern __shared__ unsigned char smem[];
    float* sD = (float*)(smem + SD_OFF);
    const uint32_t sb = smem_u32(smem);

    const int tid = threadIdx.x, wid = tid >> 5, lane = tid & 31;
    const int h = blockIdx.x, b = blockIdx.y;

    const int lo = (h - MD < 0) ? 0 : h - MD;
    const int hi = (h + MD > H - 1) ? H - 1 : h + MD;
    const int nv = hi - lo + 1;

    // ---- prologue copies: A + B0 (group), B1 (group) ----
    {
        const unsigned char* ga = gA + ((size_t)b * H + h) * IMG_BYTES;
        for (int t = tid; t < IMG_BYTES / 16; t += 256)
            CP16(sb + t * 16, (uint64_t)__cvta_generic_to_global(ga + t * 16));
        const unsigned char* gb0 = gB + ((size_t)b * H + lo) * IMG_BYTES;
        for (int t = tid; t < IMG_BYTES / 16; t += 256)
            CP16(sb + SB_OFF + t * 16, (uint64_t)__cvta_generic_to_global(gb0 + t * 16));
        CP_COMMIT();
        if (nv > 1) {
            const unsigned char* gb1 = gB + ((size_t)b * H + lo + 1) * IMG_BYTES;
            for (int t = tid; t < IMG_BYTES / 16; t += 256)
                CP16(sb + SB_OFF + IMG_BYTES + t * 16, (uint64_t)__cvta_generic_to_global(gb1 + t * 16));
            CP_COMMIT();
        }
    }

    // ---- zero slabs for out-of-range dy (overlaps the copies) ----
    {
        const float4 z = make_float4(0.f, 0.f, 0.f, 0.f);
        for (int dy = 0; dy < KD; dy++) {
            const int h2 = h + dy - MD;
            if (h2 >= 0 && h2 < H) continue;
            const size_t base = (((size_t)b * (KD * KD) + (size_t)dy * KD) * H + h) * W;
            for (int i = tid; i < KD * (W / 4); i += 256) {
                const int dx = i / (W / 4), q = i % (W / 4);
                *(float4*)(out + base + (size_t)dx * (H * W) + q * 4) = z;
            }
        }
    }

    const int mbase = (wid >> 2) * 48;      // 2 M-groups of 48 rows
    const int nbase = (wid & 3) * 24;       // 4 N-groups of 24 cols
    const float SCALE = 0.08838834764831843f;   // 1/sqrt(128)

    // ldmatrix lane address components (constant per thread)
    const int ja = lane >> 3;                           // A: matrix 0..3
    const int ra = (lane & 7) + ((ja & 1) << 3);        // A: row-in-tile 0..15
    const int ka = (ja >> 1) << 4;                      // A: +0 / +16 bytes
    const int rb = lane & 7;                            // B: row-in-tile
    const int jb = (lane >> 3) & 1;                     // B: matrix 0/1
    const int kb = jb << 4;

    for (int i = 0; i < nv; i++) {
        const int s = i & 1;
        const uint32_t sB = sb + SB_OFF + s * IMG_BYTES;

        if (i + 1 < nv) asm volatile("cp.async.wait_group 1;" ::: "memory");
        else            asm volatile("cp.async.wait_group 0;" ::: "memory");
        __syncthreads();

        // ---- GEMM: acc[m][n] = sum over k of 3-term split-bf16 ----
        float acc[3][3][4];
#pragma unroll
        for (int m = 0; m < 3; m++)
#pragma unroll
            for (int n = 0; n < 3; n++)
#pragma unroll
                for (int j = 0; j < 4; j++) acc[m][n][j] = 0.f;

#pragma unroll 2
        for (int kc = 0; kc < 8; kc++) {
            uint32_t ah[3][4], al[3][4], bh[3][2], bl[3][2];
#pragma unroll
            for (int m = 0; m < 3; m++) {
                const int row = mbase + m * 16 + ra;
                const uint32_t ad = sb + swz(row, kc * 32 + ka);
                LDMX4(ah[m][0], ah[m][1], ah[m][2], ah[m][3], ad);
                LDMX4(al[m][0], al[m][1], al[m][2], al[m][3], ad + IMG_HALF);
            }
#pragma unroll
            for (int n = 0; n < 3; n++) {
                const int row = nbase + n * 8 + rb;
                const uint32_t bd = sB + swz(row, kc * 32 + kb);
                LDMX2(bh[n][0], bh[n][1], bd);
                LDMX2(bl[n][0], bl[n][1], bd + IMG_HALF);
            }
#pragma unroll
            for (int m = 0; m < 3; m++)
#pragma unroll
                for (int n = 0; n < 3; n++) {
                    MMA(acc[m][n], ah[m], bh[n]);
                    MMA(acc[m][n], ah[m], bl[n]);
                    MMA(acc[m][n], al[m], bh[n]);
                }
        }

        // ---- stage D fragments to smem [w][w2] ----
        {
            const int tq = lane >> 2, tr = (lane & 3) * 2;
#pragma unroll
            for (int m = 0; m < 3; m++) {
                const int r = mbase + m * 16 + tq;
#pragma unroll
                for (int n = 0; n < 3; n++) {
                    const int c = nbase + n * 8 + tr;
                    *(float2*)(sD + r * DSTRIDE + c)       = make_float2(acc[m][n][0], acc[m][n][1]);
                    *(float2*)(sD + (r + 8) * DSTRIDE + c) = make_float2(acc[m][n][2], acc[m][n][3]);
                }
            }
        }
        __syncthreads();

        // prefetch B(i+2) into the slot just freed
        if (i + 2 < nv) {
            const unsigned char* gbn = gB + ((size_t)b * H + lo + i + 2) * IMG_BYTES;
            for (int t = tid; t < IMG_BYTES / 16; t += 256)
                CP16(sB + t * 16, (uint64_t)__cvta_generic_to_global(gbn + t * 16));
            CP_COMMIT();
        }

        // ---- write out[b, dy*81+dx, h, w] = scale * D[w][w+dx-40] ----
        const int dy = (lo + i) - h + MD;
        for (int t = wid; t < KD * 3; t += 8) {
            const int dx = t / 3, wc = t % 3;
            const int w = wc * 32 + lane, w2 = w + dx - MD;
            const float v = (w2 >= 0 && w2 < W) ? sD[w * DSTRIDE + w2] * SCALE : 0.f;
            out[(((size_t)b * (KD * KD) + (size_t)(dy * KD + dx)) * H + h) * W + w] = v;
        }
        // sD reuse is protected by the __syncthreads at the top of the next iter
    }
}

// ---------------- launch ----------------
extern "C" void kernel_launch(void* const* d_in, const int* in_sizes, int n_in,
                              void* d_out, int out_size)
{
    const float* x1 = (const float*)d_in[0];
    const float* x2 = (const float*)d_in[1];
    float* out = (float*)d_out;

    cudaFuncSetAttribute(prep_kernel, cudaFuncAttributeMaxDynamicSharedMemorySize, PREP_SMEM);
    cudaFuncSetAttribute(corr_main,   cudaFuncAttributeMaxDynamicSharedMemorySize, MAIN_SMEM);

    dim3 grid(H, 2);
    prep_kernel<<<grid, 256, PREP_SMEM>>>(x1, x2);
    corr_main<<<grid, 256, MAIN_SMEM>>>(out);
}

// round 9
// speedup vs baseline: 5.7001x; 1.2790x over previous
#include <cuda_runtime.h>
#include <cuda_bf16.h>
#include <cstdint>

// Correlation (FlowNet) via per-(b,h) Gram GEMMs on mma.sync (HMMA bf16).
//   out[b, dy*81+dx, h, w] = (1/sqrt(128)) * sum_c x1[b,c,h,w]*x2pad[b,c,h+dy,w+dx]
// D[w][w2] = sum_c x1[.,h,w]*x2[.,h2,w2]  (M=96, N=96, K=128, split-bf16 x3)
// out[dy][dx][w] = D[w][w+dx-40], h2 = h+dy-40.
//
// R7: 384 threads (12 warps, 3x4 tile grid of 32x24), register-double-buffered
// ldmatrix fragments, scale folded into stage, division-free epilogue.

#define MD 40
#define KD 81
#define C  128
#define H  64
#define W  96

#define IMG_HALF  24576                 // 96 rows * 256 B (bf16 [w][c], swizzled)
#define IMG_BYTES 49152                 // hi image + lo image

__device__ __align__(1024) unsigned char gA[(size_t)2 * H * IMG_BYTES];
__device__ __align__(1024) unsigned char gB[(size_t)2 * H * IMG_BYTES];

__device__ __forceinline__ uint32_t smem_u32(const void* p) {
    uint32_t a;
    asm("{ .reg .u64 t; cvta.to.shared.u64 t, %1; cvt.u32.u64 %0, t; }" : "=r"(a) : "l"(p));
    return a;
}
// swizzled byte offset of element (row=w, col=c-byte) in a [96][256B] bf16 image
__device__ __forceinline__ uint32_t swz(int row, int kbyte) {
    uint32_t off = row * 256 + kbyte;
    return off ^ ((row & 7) << 4);
}

#define CP16(sdst, gsrc) \
    asm volatile("cp.async.cg.shared.global [%0], [%1], 16;" \
        :: "r"(sdst), "l"(gsrc) : "memory")
#define CP_COMMIT() asm volatile("cp.async.commit_group;" ::: "memory")

#define LDMX4(r0,r1,r2,r3,a) \
    asm volatile("ldmatrix.sync.aligned.m8n8.x4.shared.b16 {%0,%1,%2,%3}, [%4];" \
        : "=r"(r0),"=r"(r1),"=r"(r2),"=r"(r3) : "r"(a))
#define LDMX2(r0,r1,a) \
    asm volatile("ldmatrix.sync.aligned.m8n8.x2.shared.b16 {%0,%1}, [%2];" \
        : "=r"(r0),"=r"(r1) : "r"(a))
#define MMA(d,a,b) \
    asm volatile("mma.sync.aligned.m16n8k16.row.col.f32.bf16.bf16.f32 " \
        "{%0,%1,%2,%3}, {%4,%5,%6,%7}, {%8,%9}, {%0,%1,%2,%3};" \
        : "+f"((d)[0]),"+f"((d)[1]),"+f"((d)[2]),"+f"((d)[3]) \
        : "r"((a)[0]),"r"((a)[1]),"r"((a)[2]),"r"((a)[3]), "r"((b)[0]),"r"((b)[1]))

// ---------------- kernel 1: build swizzled bf16 hi/lo images ----------------
#define STG_STRIDE 129
#define PREP_SMEM (96 * STG_STRIDE * 4 + IMG_BYTES)   // 98688

__global__ __launch_bounds__(256, 1)
void prep_kernel(const float* __restrict__ x1, const float* __restrict__ x2)
{
    extern __shared__ float ps[];                       // stage [w][STG_STRIDE] f32
    uint32_t* img = (uint32_t*)((unsigned char*)ps + 96 * STG_STRIDE * 4);

    const int h = blockIdx.x, b = blockIdx.y, tid = threadIdx.x;

    for (int t = 0; t < 2; t++) {
        const float* src = (t ? x2 : x1);
        for (int i = tid; i < C * (W / 4); i += 256) {
            const int c = i / 24, q = i % 24;
            const float4 v = *(const float4*)(src + (((size_t)b * C + c) * H + h) * W + q * 4);
            ps[(q * 4 + 0) * STG_STRIDE + c] = v.x;
            ps[(q * 4 + 1) * STG_STRIDE + c] = v.y;
            ps[(q * 4 + 2) * STG_STRIDE + c] = v.z;
            ps[(q * 4 + 3) * STG_STRIDE + c] = v.w;
        }
        __syncthreads();
        for (int i = tid; i < W * (C / 2); i += 256) {
            const int w = i >> 6, c2 = i & 63;
            const float f0 = ps[w * STG_STRIDE + 2 * c2];
            const float f1 = ps[w * STG_STRIDE + 2 * c2 + 1];
            const __nv_bfloat16 h0 = __float2bfloat16(f0);
            const __nv_bfloat16 h1 = __float2bfloat16(f1);
            const __nv_bfloat16 l0 = __float2bfloat16(f0 - __bfloat162float(h0));
            const __nv_bfloat16 l1 = __float2bfloat16(f1 - __bfloat162float(h1));
            const uint32_t hw = ((uint32_t)__bfloat16_as_ushort(h1) << 16) | __bfloat16_as_ushort(h0);
            const uint32_t lw = ((uint32_t)__bfloat16_as_ushort(l1) << 16) | __bfloat16_as_ushort(l0);
            const uint32_t sw = swz(w, c2 * 4);
            img[sw >> 2]              = hw;
            img[(IMG_HALF + sw) >> 2] = lw;
        }
        __syncthreads();
        {
            unsigned char* gdst = (t ? gB : gA) + ((size_t)b * H + h) * IMG_BYTES;
            uint4* d4 = (uint4*)gdst;
            const uint4* s4 = (const uint4*)img;
            for (int i = tid; i < IMG_BYTES / 16; i += 256) d4[i] = s4[i];
        }
        __syncthreads();
    }
}

// ---------------- kernel 2: HMMA GEMM + epilogue ----------------
#define SB_OFF   IMG_BYTES
#define SD_OFF   (3 * IMG_BYTES)                 // 147456
#define DSTRIDE  104
#define MAIN_SMEM (SD_OFF + 96 * DSTRIDE * 4)    // 187392
#define NT_MAIN  384

__global__ __launch_bounds__(NT_MAIN, 1)
void corr_main(float* __restrict__ out)
{
    extern __shared__ unsigned char smem[];
    float* sD = (float*)(smem + SD_OFF);
    const uint32_t sb = smem_u32(smem);

    const int tid = threadIdx.x, wid = tid >> 5, lane = tid & 31;
    const int h = blockIdx.x, b = blockIdx.y;

    const int lo = (h - MD < 0) ? 0 : h - MD;
    const int hi = (h + MD > H - 1) ? H - 1 : h + MD;
    const int nv = hi - lo + 1;

    // ---- prologue copies: A + B0 (group), B1 (group) ----
    {
        const unsigned char* ga = gA + ((size_t)b * H + h) * IMG_BYTES;
        for (int t = tid; t < IMG_BYTES / 16; t += NT_MAIN)
            CP16(sb + t * 16, (uint64_t)__cvta_generic_to_global(ga + t * 16));
        const unsigned char* gb0 = gB + ((size_t)b * H + lo) * IMG_BYTES;
        for (int t = tid; t < IMG_BYTES / 16; t += NT_MAIN)
            CP16(sb + SB_OFF + t * 16, (uint64_t)__cvta_generic_to_global(gb0 + t * 16));
        CP_COMMIT();
        if (nv > 1) {
            const unsigned char* gb1 = gB + ((size_t)b * H + lo + 1) * IMG_BYTES;
            for (int t = tid; t < IMG_BYTES / 16; t += NT_MAIN)
                CP16(sb + SB_OFF + IMG_BYTES + t * 16, (uint64_t)__cvta_generic_to_global(gb1 + t * 16));
            CP_COMMIT();
        }
    }

    // ---- zero slabs for out-of-range dy (overlaps the copies) ----
    {
        const float4 z = make_float4(0.f, 0.f, 0.f, 0.f);
        for (int dy = 0; dy < KD; dy++) {
            const int h2 = h + dy - MD;
            if (h2 >= 0 && h2 < H) continue;
            const size_t base = (((size_t)b * (KD * KD) + (size_t)dy * KD) * H + h) * W;
            for (int i = tid; i < KD * (W / 4); i += NT_MAIN) {
                const int dx = i / (W / 4), q = i % (W / 4);
                *(float4*)(out + base + (size_t)dx * (H * W) + q * 4) = z;
            }
        }
    }

    // 3(M) x 4(N) warp grid, 32x24 tiles
    const int mbase = (wid >> 2) * 32;      // 0,32,64
    const int nbase = (wid & 3) * 24;       // 0,24,48,72
    const float SCALE = 0.08838834764831843f;   // 1/sqrt(128)

    // ldmatrix lane address components
    const int ja = lane >> 3;
    const int ra = (lane & 7) + ((ja & 1) << 3);        // A row-in-tile 0..15
    const int ka = (ja >> 1) << 4;                      // A +0/+16 B
    const int rb = lane & 7;
    const int kb = ((lane >> 3) & 1) << 4;

    for (int i = 0; i < nv; i++) {
        const int s = i & 1;
        const uint32_t sB = sb + SB_OFF + s * IMG_BYTES;

        if (i + 1 < nv) asm volatile("cp.async.wait_group 1;" ::: "memory");
        else            asm volatile("cp.async.wait_group 0;" ::: "memory");
        __syncthreads();

        // ---- GEMM: 2(Mfrag) x 3(Nfrag), 3-term split-bf16, frag double-buffer ----
        float acc[2][3][4];
#pragma unroll
        for (int m = 0; m < 2; m++)
#pragma unroll
            for (int n = 0; n < 3; n++)
#pragma unroll
                for (int j = 0; j < 4; j++) acc[m][n][j] = 0.f;

        uint32_t ah[2][2][4], al[2][2][4], bh[2][3][2], bl[2][3][2];

        // preload kc = 0 into buffer 0
#pragma unroll
        for (int m = 0; m < 2; m++) {
            const uint32_t ad = sb + swz(mbase + m * 16 + ra, ka);
            LDMX4(ah[0][m][0], ah[0][m][1], ah[0][m][2], ah[0][m][3], ad);
            LDMX4(al[0][m][0], al[0][m][1], al[0][m][2], al[0][m][3], ad + IMG_HALF);
        }
#pragma unroll
        for (int n = 0; n < 3; n++) {
            const uint32_t bd = sB + swz(nbase + n * 8 + rb, kb);
            LDMX2(bh[0][n][0], bh[0][n][1], bd);
            LDMX2(bl[0][n][0], bl[0][n][1], bd + IMG_HALF);
        }

#pragma unroll
        for (int kc = 0; kc < 8; kc++) {
            const int cur = kc & 1, nxt = cur ^ 1;
            if (kc < 7) {
                const int kn = (kc + 1) * 32;
#pragma unroll
                for (int m = 0; m < 2; m++) {
                    const uint32_t ad = sb + swz(mbase + m * 16 + ra, kn + ka);
                    LDMX4(ah[nxt][m][0], ah[nxt][m][1], ah[nxt][m][2], ah[nxt][m][3], ad);
                    LDMX4(al[nxt][m][0], al[nxt][m][1], al[nxt][m][2], al[nxt][m][3], ad + IMG_HALF);
                }
#pragma unroll
                for (int n = 0; n < 3; n++) {
                    const uint32_t bd = sB + swz(nbase + n * 8 + rb, kn + kb);
                    LDMX2(bh[nxt][n][0], bh[nxt][n][1], bd);
                    LDMX2(bl[nxt][n][0], bl[nxt][n][1], bd + IMG_HALF);
                }
            }
#pragma unroll
            for (int m = 0; m < 2; m++)
#pragma unroll
                for (int n = 0; n < 3; n++) {
                    MMA(acc[m][n], ah[cur][m], bh[cur][n]);
                    MMA(acc[m][n], ah[cur][m], bl[cur][n]);
                    MMA(acc[m][n], al[cur][m], bh[cur][n]);
                }
        }

        // ---- stage D (scaled) to smem [w][w2] ----
        {
            const int tq = lane >> 2, tr = (lane & 3) * 2;
#pragma unroll
            for (int m = 0; m < 2; m++) {
                const int r = mbase + m * 16 + tq;
#pragma unroll
                for (int n = 0; n < 3; n++) {
                    const int c = nbase + n * 8 + tr;
                    *(float2*)(sD + r * DSTRIDE + c) =
                        make_float2(acc[m][n][0] * SCALE, acc[m][n][1] * SCALE);
                    *(float2*)(sD + (r + 8) * DSTRIDE + c) =
                        make_float2(acc[m][n][2] * SCALE, acc[m][n][3] * SCALE);
                }
            }
        }
        __syncthreads();

        // prefetch B(i+2) into the slot just freed
        if (i + 2 < nv) {
            const unsigned char* gbn = gB + ((size_t)b * H + lo + i + 2) * IMG_BYTES;
            for (int t = tid; t < IMG_BYTES / 16; t += NT_MAIN)
                CP16(sB + t * 16, (uint64_t)__cvta_generic_to_global(gbn + t * 16));
            CP_COMMIT();
        }

        // ---- write out[b, dy*81+dx, h, w] = sD[w][w+dx-40] (division-free) ----
        const int dy = (lo + i) - h + MD;
        const size_t obase = (((size_t)b * (KD * KD) + (size_t)dy * KD) * H + h) * W;
        for (int dx = wid; dx < KD; dx += 12) {
            const int d0 = dx - MD;
#pragma unroll
            for (int wc = 0; wc < 3; wc++) {
                const int w = wc * 32 + lane, w2 = w + d0;
                const float v = (w2 >= 0 && w2 < W) ? sD[w * DSTRIDE + w2] : 0.f;
                out[obase + (size_t)dx * (H * W) + w] = v;
            }
        }
        // sD reuse protected by the __syncthreads at the top of the next iter
    }
}

// ---------------- launch ----------------
extern "C" void kernel_launch(void* const* d_in, const int* in_sizes, int n_in,
                              void* d_out, int out_size)
{
    const float* x1 = (const float*)d_in[0];
    const float* x2 = (const float*)d_in[1];
    float* out = (float*)d_out;

    cudaFuncSetAttribute(prep_kernel, cudaFuncAttributeMaxDynamicSharedMemorySize, PREP_SMEM);
    cudaFuncSetAttribute(corr_main,   cudaFuncAttributeMaxDynamicSharedMemorySize, MAIN_SMEM);

    dim3 grid(H, 2);
    prep_kernel<<<grid, 256, PREP_SMEM>>>(x1, x2);
    corr_main<<<grid, NT_MAIN, MAIN_SMEM>>>(out);
}

// round 13
// speedup vs baseline: 5.8332x; 1.0233x over previous
#include <cuda_runtime.h>
#include <cuda_bf16.h>
#include <cstdint>

// Correlation (FlowNet) via per-(b,h) Gram GEMMs on mma.sync (HMMA bf16).
//   out[b, dy*81+dx, h, w] = (1/sqrt(128)) * sum_c x1[b,c,h,w]*x2pad[b,c,h+dy,w+dx]
// D[w][w2] = sum_c x1[.,h,w]*x2[.,h2,w2]  (M=96, N=96, K=128, split-bf16 x3)
// out[dy][dx][w] = D[w][w+dx-40], h2 = h+dy-40.
//
// R8: warp specialization — 8 GEMM warps (2x4 grid, 48x24 tiles, frag double
// buffer) + 4 epilogue warps, double-buffered sD, named-barrier semaphores.

#define MD 40
#define KD 81
#define C  128
#define H  64
#define W  96

#define IMG_HALF  24576                 // 96 rows * 256 B (bf16 [w][c], swizzled)
#define IMG_BYTES 49152                 // hi image + lo image

__device__ __align__(1024) unsigned char gA[(size_t)2 * H * IMG_BYTES];
__device__ __align__(1024) unsigned char gB[(size_t)2 * H * IMG_BYTES];

__device__ __forceinline__ uint32_t smem_u32(const void* p) {
    uint32_t a;
    asm("{ .reg .u64 t; cvta.to.shared.u64 t, %1; cvt.u32.u64 %0, t; }" : "=r"(a) : "l"(p));
    return a;
}
__device__ __forceinline__ uint32_t swz(int row, int kbyte) {
    uint32_t off = row * 256 + kbyte;
    return off ^ ((row & 7) << 4);
}

#define CP16(sdst, gsrc) \
    asm volatile("cp.async.cg.shared.global [%0], [%1], 16;" \
        :: "r"(sdst), "l"(gsrc) : "memory")
#define CP_COMMIT() asm volatile("cp.async.commit_group;" ::: "memory")

#define BAR_SYNC(id, cnt)   asm volatile("bar.sync %0, %1;"   :: "r"(id), "r"(cnt) : "memory")
#define BAR_ARRIVE(id, cnt) asm volatile("bar.arrive %0, %1;" :: "r"(id), "r"(cnt) : "memory")

#define LDMX4(r0,r1,r2,r3,a) \
    asm volatile("ldmatrix.sync.aligned.m8n8.x4.shared.b16 {%0,%1,%2,%3}, [%4];" \
        : "=r"(r0),"=r"(r1),"=r"(r2),"=r"(r3) : "r"(a))
#define LDMX2(r0,r1,a) \
    asm volatile("ldmatrix.sync.aligned.m8n8.x2.shared.b16 {%0,%1}, [%2];" \
        : "=r"(r0),"=r"(r1) : "r"(a))
#define MMA(d,a,b) \
    asm volatile("mma.sync.aligned.m16n8k16.row.col.f32.bf16.bf16.f32 " \
        "{%0,%1,%2,%3}, {%4,%5,%6,%7}, {%8,%9}, {%0,%1,%2,%3};" \
        : "+f"((d)[0]),"+f"((d)[1]),"+f"((d)[2]),"+f"((d)[3]) \
        : "r"((a)[0]),"r"((a)[1]),"r"((a)[2]),"r"((a)[3]), "r"((b)[0]),"r"((b)[1]))

// ---------------- kernel 1: build swizzled bf16 hi/lo images ----------------
#define STG_STRIDE 129
#define PREP_SMEM (96 * STG_STRIDE * 4 + IMG_BYTES)   // 98688

__global__ __launch_bounds__(256, 1)
void prep_kernel(const float* __restrict__ x1, const float* __restrict__ x2)
{
    extern __shared__ float ps[];
    uint32_t* img = (uint32_t*)((unsigned char*)ps + 96 * STG_STRIDE * 4);

    const int h = blockIdx.x, b = blockIdx.y, tid = threadIdx.x;

    for (int t = 0; t < 2; t++) {
        const float* src = (t ? x2 : x1);
        for (int i = tid; i < C * (W / 4); i += 256) {
            const int c = i / 24, q = i % 24;
            const float4 v = *(const float4*)(src + (((size_t)b * C + c) * H + h) * W + q * 4);
            ps[(q * 4 + 0) * STG_STRIDE + c] = v.x;
            ps[(q * 4 + 1) * STG_STRIDE + c] = v.y;
            ps[(q * 4 + 2) * STG_STRIDE + c] = v.z;
            ps[(q * 4 + 3) * STG_STRIDE + c] = v.w;
        }
        __syncthreads();
        for (int i = tid; i < W * (C / 2); i += 256) {
            const int w = i >> 6, c2 = i & 63;
            const float f0 = ps[w * STG_STRIDE + 2 * c2];
            const float f1 = ps[w * STG_STRIDE + 2 * c2 + 1];
            const __nv_bfloat16 h0 = __float2bfloat16(f0);
            const __nv_bfloat16 h1 = __float2bfloat16(f1);
            const __nv_bfloat16 l0 = __float2bfloat16(f0 - __bfloat162float(h0));
            const __nv_bfloat16 l1 = __float2bfloat16(f1 - __bfloat162float(h1));
            const uint32_t hw = ((uint32_t)__bfloat16_as_ushort(h1) << 16) | __bfloat16_as_ushort(h0);
            const uint32_t lw = ((uint32_t)__bfloat16_as_ushort(l1) << 16) | __bfloat16_as_ushort(l0);
            const uint32_t sw = swz(w, c2 * 4);
            img[sw >> 2]              = hw;
            img[(IMG_HALF + sw) >> 2] = lw;
        }
        __syncthreads();
        {
            unsigned char* gdst = (t ? gB : gA) + ((size_t)b * H + h) * IMG_BYTES;
            uint4* d4 = (uint4*)gdst;
            const uint4* s4 = (const uint4*)img;
            for (int i = tid; i < IMG_BYTES / 16; i += 256) d4[i] = s4[i];
        }
        __syncthreads();
    }
}

// ---------------- kernel 2: warp-specialized HMMA GEMM + epilogue ----------------
#define SB_OFF   IMG_BYTES
#define SD_OFF   (3 * IMG_BYTES)                 // 147456
#define DSTRIDE  104
#define SD_BYTES (96 * DSTRIDE * 4)              // 39936
#define MAIN_SMEM (SD_OFF + 2 * SD_BYTES)        // 227328
#define NT_MAIN  384
#define NPROD    256                             // 8 GEMM warps

__global__ __launch_bounds__(NT_MAIN, 1)
void corr_main(float* __restrict__ out)
{
    extern __shared__ unsigned char smem[];
    const uint32_t sb = smem_u32(smem);

    const int tid = threadIdx.x, wid = tid >> 5, lane = tid & 31;
    const int h = blockIdx.x, b = blockIdx.y;

    const int lo = (h - MD < 0) ? 0 : h - MD;
    const int hi = (h + MD > H - 1) ? H - 1 : h + MD;
    const int nv = hi - lo + 1;
    const float SCALE = 0.08838834764831843f;   // 1/sqrt(128)

    if (wid < 8) {
        // =================== producers: copies + GEMM + stage ===================
        // prologue: A + B0 (group 0), B1 (group 1)
        {
            const unsigned char* ga = gA + ((size_t)b * H + h) * IMG_BYTES;
            for (int t = tid; t < IMG_BYTES / 16; t += NPROD)
                CP16(sb + t * 16, (uint64_t)__cvta_generic_to_global(ga + t * 16));
            const unsigned char* gb0 = gB + ((size_t)b * H + lo) * IMG_BYTES;
            for (int t = tid; t < IMG_BYTES / 16; t += NPROD)
                CP16(sb + SB_OFF + t * 16, (uint64_t)__cvta_generic_to_global(gb0 + t * 16));
            CP_COMMIT();
            if (nv > 1) {
                const unsigned char* gb1 = gB + ((size_t)b * H + lo + 1) * IMG_BYTES;
                for (int t = tid; t < IMG_BYTES / 16; t += NPROD)
                    CP16(sb + SB_OFF + IMG_BYTES + t * 16, (uint64_t)__cvta_generic_to_global(gb1 + t * 16));
                CP_COMMIT();
            }
        }

        // 2(M) x 4(N) warp grid, 48x24 tiles
        const int mbase = (wid >> 2) * 48;
        const int nbase = (wid & 3) * 24;

        const int ja = lane >> 3;
        const int ra = (lane & 7) + ((ja & 1) << 3);
        const int ka = (ja >> 1) << 4;
        const int rb = lane & 7;
        const int kb = ((lane >> 3) & 1) << 4;
        const int tq = lane >> 2, tr = (lane & 3) * 2;

        for (int i = 0; i < nv; i++) {
            const int s = i & 1;
            const uint32_t sB = sb + SB_OFF + s * IMG_BYTES;
            float* sDp = (float*)(smem + SD_OFF + s * SD_BYTES);

            if (i + 1 < nv) asm volatile("cp.async.wait_group 1;" ::: "memory");
            else            asm volatile("cp.async.wait_group 0;" ::: "memory");
            BAR_SYNC(1, NPROD);                 // B(i) visible to all producers

            // ---- GEMM: 3(M) x 3(N) frags, 3-term split-bf16, frag double-buffer ----
            float acc[3][3][4];
#pragma unroll
            for (int m = 0; m < 3; m++)
#pragma unroll
                for (int n = 0; n < 3; n++)
#pragma unroll
                    for (int j = 0; j < 4; j++) acc[m][n][j] = 0.f;

            uint32_t ah[2][3][4], al[2][3][4], bh[2][3][2], bl[2][3][2];
#pragma unroll
            for (int m = 0; m < 3; m++) {
                const uint32_t ad = sb + swz(mbase + m * 16 + ra, ka);
                LDMX4(ah[0][m][0], ah[0][m][1], ah[0][m][2], ah[0][m][3], ad);
                LDMX4(al[0][m][0], al[0][m][1], al[0][m][2], al[0][m][3], ad + IMG_HALF);
            }
#pragma unroll
            for (int n = 0; n < 3; n++) {
                const uint32_t bd = sB + swz(nbase + n * 8 + rb, kb);
                LDMX2(bh[0][n][0], bh[0][n][1], bd);
                LDMX2(bl[0][n][0], bl[0][n][1], bd + IMG_HALF);
            }

#pragma unroll
            for (int kc = 0; kc < 8; kc++) {
                const int cur = kc & 1, nxt = cur ^ 1;
                if (kc < 7) {
                    const int kn = (kc + 1) * 32;
#pragma unroll
                    for (int m = 0; m < 3; m++) {
                        const uint32_t ad = sb + swz(mbase + m * 16 + ra, kn + ka);
                        LDMX4(ah[nxt][m][0], ah[nxt][m][1], ah[nxt][m][2], ah[nxt][m][3], ad);
                        LDMX4(al[nxt][m][0], al[nxt][m][1], al[nxt][m][2], al[nxt][m][3], ad + IMG_HALF);
                    }
#pragma unroll
                    for (int n = 0; n < 3; n++) {
                        const uint32_t bd = sB + swz(nbase + n * 8 + rb, kn + kb);
                        LDMX2(bh[nxt][n][0], bh[nxt][n][1], bd);
                        LDMX2(bl[nxt][n][0], bl[nxt][n][1], bd + IMG_HALF);
                    }
                }
#pragma unroll
                for (int m = 0; m < 3; m++)
#pragma unroll
                    for (int n = 0; n < 3; n++) {
                        MMA(acc[m][n], ah[cur][m], bh[cur][n]);
                        MMA(acc[m][n], ah[cur][m], bl[cur][n]);
                        MMA(acc[m][n], al[cur][m], bh[cur][n]);
                    }
            }

            // ---- stage D (scaled) into sD[s] once it is free ----
            if (i >= 2) BAR_SYNC(4 + s, NT_MAIN);   // consumer freed this buffer
#pragma unroll
            for (int m = 0; m < 3; m++) {
                const int r = mbase + m * 16 + tq;
#pragma unroll
                for (int n = 0; n < 3; n++) {
                    const int c = nbase + n * 8 + tr;
                    *(float2*)(sDp + r * DSTRIDE + c) =
                        make_float2(acc[m][n][0] * SCALE, acc[m][n][1] * SCALE);
                    *(float2*)(sDp + (r + 8) * DSTRIDE + c) =
                        make_float2(acc[m][n][2] * SCALE, acc[m][n][3] * SCALE);
                }
            }
            BAR_ARRIVE(2 + s, NT_MAIN);             // signal full

            BAR_SYNC(1, NPROD);                     // all producers done with sB[s]
            if (i + 2 < nv) {
                const unsigned char* gbn = gB + ((size_t)b * H + lo + i + 2) * IMG_BYTES;
                for (int t = tid; t < IMG_BYTES / 16; t += NPROD)
                    CP16(sB + t * 16, (uint64_t)__cvta_generic_to_global(gbn + t * 16));
                CP_COMMIT();
            }
        }
    } else {
        // =================== consumers: zero slabs + epilogue ===================
        const int etid = tid - NPROD;               // 0..127
        const int ewid = wid - 8;                   // 0..3
        {
            const float4 z = make_float4(0.f, 0.f, 0.f, 0.f);
            for (int dy = 0; dy < KD; dy++) {
                const int h2 = h + dy - MD;
                if (h2 >= 0 && h2 < H) continue;
                const size_t base = (((size_t)b * (KD * KD) + (size_t)dy * KD) * H + h) * W;
                for (int i = etid; i < KD * (W / 4); i += 128) {
                    const int dx = i / (W / 4), q = i % (W / 4);
                    *(float4*)(out + base + (size_t)dx * (H * W) + q * 4) = z;
                }
            }
        }

        for (int i = 0; i < nv; i++) {
            const int p = i & 1;
            const float* sDp = (const float*)(smem + SD_OFF + p * SD_BYTES);
            BAR_SYNC(2 + p, NT_MAIN);               // wait full

            const int dy = (lo + i) - h + MD;
            const size_t obase = (((size_t)b * (KD * KD) + (size_t)dy * KD) * H + h) * W;
            for (int dx = ewid; dx < KD; dx += 4) {
                const int d0 = dx - MD;
#pragma unroll
                for (int wc = 0; wc < 3; wc++) {
                    const int w = wc * 32 + lane, w2 = w + d0;
                    const float v = (w2 >= 0 && w2 < W) ? sDp[w * DSTRIDE + w2] : 0.f;
                    out[obase + (size_t)dx * (H * W) + w] = v;
                }
            }
            BAR_ARRIVE(4 + p, NT_MAIN);             // signal empty
        }
    }
}

// ---------------- launch ----------------
extern "C" void kernel_launch(void* const* d_in, const int* in_sizes, int n_in,
                              void* d_out, int out_size)
{
    const float* x1 = (const float*)d_in[0];
    const float* x2 = (const float*)d_in[1];
    float* out = (float*)d_out;

    cudaFuncSetAttribute(prep_kernel, cudaFuncAttributeMaxDynamicSharedMemorySize, PREP_SMEM);
    cudaFuncSetAttribute(corr_main,   cudaFuncAttributeMaxDynamicSharedMemorySize, MAIN_SMEM);

    dim3 grid(H, 2);
    prep_kernel<<<grid, 256, PREP_SMEM>>>(x1, x2);
    corr_main<<<grid, NT_MAIN, MAIN_SMEM>>>(out);
}